// round 1
// baseline (speedup 1.0000x reference)
#include <cuda_runtime.h>
#include <math.h>

#define DEV_INLINE __device__ __forceinline__

// Problem constants (fixed by the dataset)
constexpr int B_  = 8;
constexpr int C_  = 64;
constexpr int T_  = 192;
constexpr int FR_ = 128;
constexpr int LT  = 192;              // time mode L
constexpr int LF  = 128;              // freq mode L
constexpr int DT  = C_ * FR_;         // 8192
constexpr int DF  = C_ * T_;          // 12288
constexpr int KC  = 32;               // k-chunk
constexpr int TILE = 64;

// ---------------- device scratch (no allocations allowed) ----------------
// split-K partial gram buffers (summed deterministically in finalize)
__device__ float g_pTs[2 * B_ * LT * LT];
__device__ float g_pTt[2 * B_ * LT * LT];
__device__ float g_pFs[3 * B_ * LF * LF];
__device__ float g_pFt[3 * B_ * LF * LF];

// per-matrix derived quantities
__device__ float g_logP_Ts[B_ * LT * LT];
__device__ float g_PtrT_Ts[B_ * LT * LT];
__device__ float g_logP_Tt[B_ * LT * LT];
__device__ float g_PtrT_Tt[B_ * LT * LT];
__device__ float g_logP_Fs[B_ * LF * LF];
__device__ float g_PtrT_Fs[B_ * LF * LF];
__device__ float g_logP_Ft[B_ * LF * LF];
__device__ float g_PtrT_Ft[B_ * LF * LF];

__device__ float g_ent_Ts[B_ * LT], g_ent_Tt[B_ * LT];
__device__ float g_ent_Fs[B_ * LF], g_ent_Ft[B_ * LF];
__device__ float g_rm_Ts[B_ * LT],  g_rm_Tt[B_ * LT];
__device__ float g_rm_Fs[B_ * LF],  g_rm_Ft[B_ * LF];

__device__ float g_qT[B_ * LT * 4], g_kT[B_ * LT * 4];
__device__ float g_qF[B_ * LF * 4], g_kF[B_ * LF * 4];

__device__ float g_partials[B_ * LT + B_ * LF];  // 1536 + 1024

__constant__ int c_tpi[6] = {0, 0, 0, 1, 1, 2};
__constant__ int c_tpj[6] = {0, 1, 2, 1, 2, 2};
__constant__ int c_fpi[3] = {0, 0, 1};
__constant__ int c_fpj[3] = {0, 1, 1};

// ---------------- block reductions ----------------
template <int NW>
DEV_INLINE float blockReduceSum(float v, float* red) {
#pragma unroll
    for (int o = 16; o > 0; o >>= 1) v += __shfl_xor_sync(0xffffffffu, v, o);
    if ((threadIdx.x & 31) == 0) red[threadIdx.x >> 5] = v;
    __syncthreads();
    float r = red[0];
#pragma unroll
    for (int i = 1; i < NW; i++) r += red[i];
    __syncthreads();
    return r;
}

template <int NW>
DEV_INLINE float blockReduceMax(float v, float* red) {
#pragma unroll
    for (int o = 16; o > 0; o >>= 1) v = fmaxf(v, __shfl_xor_sync(0xffffffffu, v, o));
    if ((threadIdx.x & 31) == 0) red[threadIdx.x >> 5] = v;
    __syncthreads();
    float r = red[0];
#pragma unroll
    for (int i = 1; i < NW; i++) r = fmaxf(r, red[i]);
    __syncthreads();
    return r;
}

// ---------------- gram (SYRK-style, fp32, split-K, symmetric tiles) ----------------
// MODE 0 = time: row l = t, d = c*FR + f  (contiguous along f within a c)
// MODE 1 = freq: row l = f, d = c*T  + t  (contiguous along f across rows)
template <int MODE>
DEV_INLINE void gram_body(const float* __restrict__ feat, float* __restrict__ outp,
                          int b, int i0, int j0, int q0, int L) {
    __shared__ __align__(16) float As[KC][TILE + 4];
    __shared__ __align__(16) float Bs[KC][TILE + 4];
    const int tid = threadIdx.x;
    const int tx = tid & 15;          // 16 col groups of 4
    const int ty = tid >> 4;          // 8 row groups of 8
    float acc[8][4];
#pragma unroll
    for (int r = 0; r < 8; r++)
#pragma unroll
        for (int c = 0; c < 4; c++) acc[r][c] = 0.f;

    for (int q = q0; q < q0 + 128; q++) {
        if (MODE == 0) {
            const int cc = q >> 2;
            const int f0 = (q & 3) * 32;
            const float* base = feat + ((size_t)(b * C_ + cc)) * (T_ * FR_) + f0;
#pragma unroll
            for (int u = 0; u < 16; u++) {
                int idx = u * 128 + tid;
                int k = idx & 31, m = idx >> 5;   // coalesced along k (f)
                As[k][m] = __ldg(base + (i0 + m) * FR_ + k);
                Bs[k][m] = __ldg(base + (j0 + m) * FR_ + k);
            }
        } else {
            const int cc = q / 6;
            const int t0 = (q - cc * 6) * 32;
            const float* base = feat + ((size_t)(b * C_ + cc)) * (T_ * FR_) + (size_t)t0 * FR_;
#pragma unroll
            for (int u = 0; u < 4; u++) {
                int idx = u * 128 + tid;
                int m4 = idx & 15, k = idx >> 4;  // coalesced along m (f), float4
                *(float4*)&As[k][m4 * 4] = *(const float4*)(base + (size_t)k * FR_ + i0 + m4 * 4);
                *(float4*)&Bs[k][m4 * 4] = *(const float4*)(base + (size_t)k * FR_ + j0 + m4 * 4);
            }
        }
        __syncthreads();
#pragma unroll 8
        for (int k = 0; k < KC; k++) {
            float4 bv = *(const float4*)&Bs[k][tx * 4];
            float4 a0 = *(const float4*)&As[k][ty * 8];
            float4 a1 = *(const float4*)&As[k][ty * 8 + 4];
            float av[8] = {a0.x, a0.y, a0.z, a0.w, a1.x, a1.y, a1.z, a1.w};
            float bw[4] = {bv.x, bv.y, bv.z, bv.w};
#pragma unroll
            for (int r = 0; r < 8; r++)
#pragma unroll
                for (int c = 0; c < 4; c++) acc[r][c] = fmaf(av[r], bw[c], acc[r][c]);
        }
        __syncthreads();
    }

    float* Gb = outp + (size_t)b * L * L;
#pragma unroll
    for (int r = 0; r < 8; r++) {
        int gi = i0 + ty * 8 + r;
#pragma unroll
        for (int c = 0; c < 4; c++) {
            int gj = j0 + tx * 4 + c;
            Gb[(size_t)gi * L + gj] = acc[r][c];
            if (i0 != j0) Gb[(size_t)gj * L + gi] = acc[r][c];
        }
    }
}

// combos: 0..23 time (2 mats x 6 pairs x 2 ksplit), 24..41 freq (2 mats x 3 pairs x 3 ksplit)
__global__ __launch_bounds__(128) void gram_kernel(const float* __restrict__ fs,
                                                   const float* __restrict__ ft) {
    const int bx = blockIdx.x;
    const int b  = blockIdx.y;
    if (bx < 24) {
        int mat = bx / 12, r = bx % 12, pair = r % 6, kp = r / 6;
        const float* feat = mat ? ft : fs;
        float* outp = (mat ? g_pTt : g_pTs) + (size_t)kp * (B_ * LT * LT);
        gram_body<0>(feat, outp, b, c_tpi[pair] * 64, c_tpj[pair] * 64, kp * 128, LT);
    } else {
        int e = bx - 24;
        int mat = e / 9, r = e % 9, pair = r % 3, kp = r / 3;
        const float* feat = mat ? ft : fs;
        float* outp = (mat ? g_pFt : g_pFs) + (size_t)kp * (B_ * LF * LF);
        gram_body<1>(feat, outp, b, c_fpi[pair] * 64, c_fpj[pair] * 64, kp * 128, LF);
    }
}

// ---------------- finalize: normalize, (P+1)/2, rowmean, softmax, logP, ent ----------------
template <int L, int NP>
__global__ void finalize_kernel(const float* __restrict__ Gp,
                                float* __restrict__ logP, float* __restrict__ PtrT,
                                float* __restrict__ ent, float* __restrict__ rm) {
    const int s = blockIdx.x, b = blockIdx.y, j = threadIdx.x;
    __shared__ float invn[L];
    __shared__ float red[L / 32];
    const int MM = L * L;

    float gd = Gp[(size_t)b * MM + (size_t)j * L + j];
#pragma unroll
    for (int p = 1; p < NP; p++)
        gd += Gp[(size_t)p * B_ * MM + (size_t)b * MM + (size_t)j * L + j];
    invn[j] = 1.0f / fmaxf(sqrtf(gd), 1e-8f);
    __syncthreads();

    float g = Gp[(size_t)b * MM + (size_t)s * L + j];
#pragma unroll
    for (int p = 1; p < NP; p++)
        g += Gp[(size_t)p * B_ * MM + (size_t)b * MM + (size_t)s * L + j];
    float P = (g * invn[s] * invn[j] + 1.0f) * 0.5f;

    float rsum = blockReduceSum<L / 32>(P, red);
    float mx   = blockReduceMax<L / 32>(P, red);
    float e    = expf(P - mx);
    float Z    = blockReduceSum<L / 32>(e, red);
    float p    = e / Z;                       // softmax
    float lp   = logf(p + 2e-8f);             // log(softmax + EPS + EPS)
    logP[(size_t)b * MM + (size_t)s * L + j] = lp;
    PtrT[(size_t)b * MM + (size_t)j * L + s] = p + 1e-8f;   // transposed Prow (+EPS)
    float es = blockReduceSum<L / 32>((p + 1e-8f) * lp, red);
    if (j == 0) {
        ent[b * L + s] = es;
        rm[b * L + s]  = rsum * (1.0f / (float)L);
    }
}

// ---------------- tiny MLP: Linear(1,4) + ReLU + LayerNorm(4) ----------------
__global__ void mlp_kernel(const float* __restrict__ rm, const float* __restrict__ W,
                           const float* __restrict__ bv, const float* __restrict__ gv,
                           const float* __restrict__ betav, float* __restrict__ outq, int n) {
    int i = blockIdx.x * 256 + threadIdx.x;
    if (i >= n) return;
    float x = rm[i];
    float h[4];
#pragma unroll
    for (int t = 0; t < 4; t++) h[t] = fmaxf(fmaf(x, W[t], bv[t]), 0.f);
    float mu = 0.25f * (h[0] + h[1] + h[2] + h[3]);
    float v = 0.f;
#pragma unroll
    for (int t = 0; t < 4; t++) { float d = h[t] - mu; v = fmaf(d, d, v); }
    v *= 0.25f;
    float inv = 1.0f / sqrtf(v + 1e-5f);
#pragma unroll
    for (int t = 0; t < 4; t++) outq[i * 4 + t] = gv[t] * (h[t] - mu) * inv + betav[t];
}

// ---------------- loss: alpha softmax + weighted KL, one block per (b, s) ----------------
template <int L>
__global__ void loss_kernel(const float* __restrict__ q, const float* __restrict__ kk,
                            const float* __restrict__ logPs, const float* __restrict__ PtT,
                            const float* __restrict__ ent, float* __restrict__ partials,
                            float invden) {
    const int s = blockIdx.x, b = blockIdx.y, t = threadIdx.x;
    __shared__ float sh_lp[L];
    __shared__ float red[L / 32];
    const int MM = L * L;

    sh_lp[t] = logPs[(size_t)b * MM + (size_t)s * L + t];
    const float* qs = q + (b * L + s) * 4;
    const float* kt = kk + (b * L + t) * 4;
    float attn = (qs[0] * kt[0] + qs[1] * kt[1] + qs[2] * kt[2] + qs[3] * kt[3]) * 0.5f;
    __syncthreads();

    float mx = blockReduceMax<L / 32>(attn, red);
    float e  = expf(attn - mx);
    float Z  = blockReduceSum<L / 32>(e, red);

    float cross = 0.f;
    const float* Pt = PtT + (size_t)b * MM;     // [k][t] layout -> coalesced over t
#pragma unroll 4
    for (int k2 = 0; k2 < L; k2++) cross = fmaf(Pt[(size_t)k2 * L + t], sh_lp[k2], cross);

    float val = e * (ent[b * L + t] - cross);
    float S = blockReduceSum<L / 32>(val, red);
    if (t == 0) partials[b * L + s] = (S / Z) * invden;
}

// ---------------- final deterministic reduce ----------------
__global__ void reduce_kernel(const float* __restrict__ partials, int n, float* __restrict__ out) {
    __shared__ float red[8];
    float v = 0.f;
    for (int i = threadIdx.x; i < n; i += 256) v += partials[i];
    float S = blockReduceSum<8>(v, red);
    if (threadIdx.x == 0) out[0] = S;
}

// ---------------- launch ----------------
extern "C" void kernel_launch(void* const* d_in, const int* in_sizes, int n_in,
                              void* d_out, int out_size) {
    const float* fs  = (const float*)d_in[0];
    const float* ft  = (const float*)d_in[1];
    const float* WqT = (const float*)d_in[2];
    const float* bqT = (const float*)d_in[3];
    const float* gqT = (const float*)d_in[4];
    const float* BqT = (const float*)d_in[5];
    const float* WkT = (const float*)d_in[6];
    const float* bkT = (const float*)d_in[7];
    const float* gkT = (const float*)d_in[8];
    const float* BkT = (const float*)d_in[9];
    const float* WqF = (const float*)d_in[10];
    const float* bqF = (const float*)d_in[11];
    const float* gqF = (const float*)d_in[12];
    const float* BqF = (const float*)d_in[13];
    const float* WkF = (const float*)d_in[14];
    const float* bkF = (const float*)d_in[15];
    const float* gkF = (const float*)d_in[16];
    const float* BkF = (const float*)d_in[17];
    float* out = (float*)d_out;

    float *pTs, *pTt, *pFs, *pFt;
    float *lpTs, *ptTs, *lpTt, *ptTt, *lpFs, *ptFs, *lpFt, *ptFt;
    float *enTs, *enTt, *enFs, *enFt, *rmTs, *rmTt, *rmFs, *rmFt;
    float *qT, *kT, *qF, *kF, *parts;
    cudaGetSymbolAddress((void**)&pTs, g_pTs);
    cudaGetSymbolAddress((void**)&pTt, g_pTt);
    cudaGetSymbolAddress((void**)&pFs, g_pFs);
    cudaGetSymbolAddress((void**)&pFt, g_pFt);
    cudaGetSymbolAddress((void**)&lpTs, g_logP_Ts);
    cudaGetSymbolAddress((void**)&ptTs, g_PtrT_Ts);
    cudaGetSymbolAddress((void**)&lpTt, g_logP_Tt);
    cudaGetSymbolAddress((void**)&ptTt, g_PtrT_Tt);
    cudaGetSymbolAddress((void**)&lpFs, g_logP_Fs);
    cudaGetSymbolAddress((void**)&ptFs, g_PtrT_Fs);
    cudaGetSymbolAddress((void**)&lpFt, g_logP_Ft);
    cudaGetSymbolAddress((void**)&ptFt, g_PtrT_Ft);
    cudaGetSymbolAddress((void**)&enTs, g_ent_Ts);
    cudaGetSymbolAddress((void**)&enTt, g_ent_Tt);
    cudaGetSymbolAddress((void**)&enFs, g_ent_Fs);
    cudaGetSymbolAddress((void**)&enFt, g_ent_Ft);
    cudaGetSymbolAddress((void**)&rmTs, g_rm_Ts);
    cudaGetSymbolAddress((void**)&rmTt, g_rm_Tt);
    cudaGetSymbolAddress((void**)&rmFs, g_rm_Fs);
    cudaGetSymbolAddress((void**)&rmFt, g_rm_Ft);
    cudaGetSymbolAddress((void**)&qT, g_qT);
    cudaGetSymbolAddress((void**)&kT, g_kT);
    cudaGetSymbolAddress((void**)&qF, g_qF);
    cudaGetSymbolAddress((void**)&kF, g_kF);
    cudaGetSymbolAddress((void**)&parts, g_partials);

    // 1) all four grams in one launch: 42 combos x 8 batches
    gram_kernel<<<dim3(42, B_), 128>>>(fs, ft);

    // 2) finalize each matrix (sum split-K partials deterministically)
    finalize_kernel<LT, 2><<<dim3(LT, B_), LT>>>(pTs, lpTs, ptTs, enTs, rmTs);
    finalize_kernel<LT, 2><<<dim3(LT, B_), LT>>>(pTt, lpTt, ptTt, enTt, rmTt);
    finalize_kernel<LF, 3><<<dim3(LF, B_), LF>>>(pFs, lpFs, ptFs, enFs, rmFs);
    finalize_kernel<LF, 3><<<dim3(LF, B_), LF>>>(pFt, lpFt, ptFt, enFt, rmFt);

    // 3) tiny MLPs
    const int nT = B_ * LT, nF = B_ * LF;
    mlp_kernel<<<(nT + 255) / 256, 256>>>(rmTs, WqT, bqT, gqT, BqT, qT, nT);
    mlp_kernel<<<(nT + 255) / 256, 256>>>(rmTt, WkT, bkT, gkT, BkT, kT, nT);
    mlp_kernel<<<(nF + 255) / 256, 256>>>(rmFs, WqF, bqF, gqF, BqF, qF, nF);
    mlp_kernel<<<(nF + 255) / 256, 256>>>(rmFt, WkF, bkF, gkF, BkF, kF, nF);

    // 4) attention-weighted KL
    const float invdenT = (float)(1.0 / ((double)B_ * LT * LT + 1e-8));
    const float invdenF = (float)(1.0 / ((double)B_ * LF * LF + 1e-8));
    loss_kernel<LT><<<dim3(LT, B_), LT>>>(qT, kT, lpTs, ptTt, enTt, parts, invdenT);
    loss_kernel<LF><<<dim3(LF, B_), LF>>>(qF, kF, lpFs, ptFt, enFt, parts + nT, invdenF);

    // 5) deterministic final reduce
    reduce_kernel<<<1, 256>>>(parts, nT + nF, out);
}

// round 3
// speedup vs baseline: 1.6078x; 1.6078x over previous
#include <cuda_runtime.h>
#include <cuda_bf16.h>
#include <stdint.h>
#include <math.h>

#define DEV_INLINE __device__ __forceinline__

// Problem constants (fixed by the dataset)
constexpr int B_  = 8;
constexpr int C_  = 64;
constexpr int T_  = 192;
constexpr int FR_ = 128;
constexpr int LT  = 192;              // time mode L
constexpr int LF  = 128;              // freq mode L
constexpr int DT  = C_ * FR_;         // 8192
constexpr int DF  = C_ * T_;          // 12288

// ---------------- device scratch (no allocations allowed) ----------------
// bf16 hi/lo rearranged copies of the two feature tensors
__device__ __align__(16) __nv_bfloat16 g_AT_s_hi[B_ * LT * DT];
__device__ __align__(16) __nv_bfloat16 g_AT_s_lo[B_ * LT * DT];
__device__ __align__(16) __nv_bfloat16 g_AT_t_hi[B_ * LT * DT];
__device__ __align__(16) __nv_bfloat16 g_AT_t_lo[B_ * LT * DT];
__device__ __align__(16) __nv_bfloat16 g_AF_s_hi[B_ * LF * DF];
__device__ __align__(16) __nv_bfloat16 g_AF_s_lo[B_ * LF * DF];
__device__ __align__(16) __nv_bfloat16 g_AF_t_hi[B_ * LF * DF];
__device__ __align__(16) __nv_bfloat16 g_AF_t_lo[B_ * LF * DF];

// split-K partial gram buffers (summed deterministically in finalize)
__device__ float g_pTs[2 * B_ * LT * LT];
__device__ float g_pTt[2 * B_ * LT * LT];
__device__ float g_pFs[3 * B_ * LF * LF];
__device__ float g_pFt[3 * B_ * LF * LF];

// per-matrix derived quantities
__device__ float g_logP_Ts[B_ * LT * LT];
__device__ float g_PtrT_Ts[B_ * LT * LT];
__device__ float g_logP_Tt[B_ * LT * LT];
__device__ float g_PtrT_Tt[B_ * LT * LT];
__device__ float g_logP_Fs[B_ * LF * LF];
__device__ float g_PtrT_Fs[B_ * LF * LF];
__device__ float g_logP_Ft[B_ * LF * LF];
__device__ float g_PtrT_Ft[B_ * LF * LF];

__device__ float g_ent_Ts[B_ * LT], g_ent_Tt[B_ * LT];
__device__ float g_ent_Fs[B_ * LF], g_ent_Ft[B_ * LF];
__device__ float g_rm_Ts[B_ * LT],  g_rm_Tt[B_ * LT];
__device__ float g_rm_Fs[B_ * LF],  g_rm_Ft[B_ * LF];

__device__ float g_qT[B_ * LT * 4], g_kT[B_ * LT * 4];
__device__ float g_qF[B_ * LF * 4], g_kF[B_ * LF * 4];

__device__ float g_partials[B_ * LT + B_ * LF];

__constant__ int c_tpi[6] = {0, 0, 0, 1, 1, 2};
__constant__ int c_tpj[6] = {0, 1, 2, 1, 2, 2};
__constant__ int c_fpi[3] = {0, 0, 1};
__constant__ int c_fpj[3] = {0, 1, 1};

// ---------------- block reductions ----------------
template <int NW>
DEV_INLINE float blockReduceSum(float v, float* red) {
#pragma unroll
    for (int o = 16; o > 0; o >>= 1) v += __shfl_xor_sync(0xffffffffu, v, o);
    if ((threadIdx.x & 31) == 0) red[threadIdx.x >> 5] = v;
    __syncthreads();
    float r = red[0];
#pragma unroll
    for (int i = 1; i < NW; i++) r += red[i];
    __syncthreads();
    return r;
}

template <int NW>
DEV_INLINE float blockReduceMax(float v, float* red) {
#pragma unroll
    for (int o = 16; o > 0; o >>= 1) v = fmaxf(v, __shfl_xor_sync(0xffffffffu, v, o));
    if ((threadIdx.x & 31) == 0) red[threadIdx.x >> 5] = v;
    __syncthreads();
    float r = red[0];
#pragma unroll
    for (int i = 1; i < NW; i++) r = fmaxf(r, red[i]);
    __syncthreads();
    return r;
}

// ---------------- prepass: fp32 -> bf16 hi/lo in time+freq layouts ----------------
// Block handles one (tensor, b, c, tchunk of 32): tile (32 t x 128 f).
// Emits: time layout [b][t][c*128+f]  and  freq layout [b][f][c*192+t].
union U4pack { __nv_bfloat16 x[4]; uint2 v; };
union U8pack { __nv_bfloat16 x[8]; uint4 v; };

__global__ __launch_bounds__(256) void prep_kernel(const float* __restrict__ fs,
                                                   const float* __restrict__ ft) {
    const int c   = blockIdx.x / 6;
    const int tch = blockIdx.x % 6;
    const int b   = blockIdx.y;
    const int tz  = blockIdx.z;
    const int t0  = tch * 32;
    const int tid = threadIdx.x;

    const float* src = tz ? ft : fs;
    __nv_bfloat16* ATh = tz ? g_AT_t_hi : g_AT_s_hi;
    __nv_bfloat16* ATl = tz ? g_AT_t_lo : g_AT_s_lo;
    __nv_bfloat16* AFh = tz ? g_AF_t_hi : g_AF_s_hi;
    __nv_bfloat16* AFl = tz ? g_AF_t_lo : g_AF_s_lo;

    __shared__ __align__(16) float s[32][132];

    const float* base = src + ((size_t)(b * C_ + c) * T_ + t0) * FR_;
#pragma unroll
    for (int u = 0; u < 4; u++) {
        int idx = u * 256 + tid;
        int r = idx >> 5, q = idx & 31;
        *(float4*)&s[r][q * 4] = *(const float4*)(base + (size_t)r * FR_ + q * 4);
    }
    __syncthreads();

    // time-layout writes: [b][t][c*128+f]
#pragma unroll
    for (int u = 0; u < 4; u++) {
        int idx = u * 256 + tid;
        int r = idx >> 5, q = idx & 31;
        float4 v = *(const float4*)&s[r][q * 4];
        U4pack hp, lp;
        float vv[4] = {v.x, v.y, v.z, v.w};
#pragma unroll
        for (int i = 0; i < 4; i++) {
            __nv_bfloat16 hb = __float2bfloat16_rn(vv[i]);
            hp.x[i] = hb;
            lp.x[i] = __float2bfloat16_rn(vv[i] - __bfloat162float(hb));
        }
        size_t off = ((size_t)(b * T_ + t0 + r) * C_ + c) * FR_ + q * 4;
        *(uint2*)(ATh + off) = hp.v;
        *(uint2*)(ATl + off) = lp.v;
    }

    // freq-layout writes: [b][f][c*192+t]  (transpose out of smem)
    const int f = tid >> 1;
    const int h = tid & 1;
#pragma unroll
    for (int g = 0; g < 2; g++) {
        int tl = h * 16 + g * 8;
        U8pack hp, lp;
#pragma unroll
        for (int i = 0; i < 8; i++) {
            float vv = s[tl + i][f];
            __nv_bfloat16 hb = __float2bfloat16_rn(vv);
            hp.x[i] = hb;
            lp.x[i] = __float2bfloat16_rn(vv - __bfloat162float(hb));
        }
        size_t off = ((size_t)(b * FR_ + f) * C_ + c) * T_ + t0 + tl;
        *(uint4*)(AFh + off) = hp.v;
        *(uint4*)(AFl + off) = lp.v;
    }
}

// ---------------- tensor-core gram (mma.sync bf16, 3-term split) ----------------
#define LDX4(R, PTR)                                                                   \
    {                                                                                  \
        unsigned int _a = (unsigned int)__cvta_generic_to_shared(PTR);                 \
        asm volatile("ldmatrix.sync.aligned.m8n8.x4.shared.b16 {%0,%1,%2,%3}, [%4];"   \
                     : "=r"((R)[0]), "=r"((R)[1]), "=r"((R)[2]), "=r"((R)[3])          \
                     : "r"(_a));                                                       \
    }

#define MMA16816(D, A, B0, B1)                                                          \
    asm volatile(                                                                       \
        "mma.sync.aligned.m16n8k16.row.col.f32.bf16.bf16.f32 "                          \
        "{%0,%1,%2,%3}, {%4,%5,%6,%7}, {%8,%9}, {%0,%1,%2,%3};"                         \
        : "+f"((D)[0]), "+f"((D)[1]), "+f"((D)[2]), "+f"((D)[3])                        \
        : "r"((A)[0]), "r"((A)[1]), "r"((A)[2]), "r"((A)[3]), "r"(B0), "r"(B1));

DEV_INLINE void gram_mma_body(const __nv_bfloat16* __restrict__ Ah,
                              const __nv_bfloat16* __restrict__ Al,
                              const __nv_bfloat16* __restrict__ Bh,
                              const __nv_bfloat16* __restrict__ Bl,
                              int ldK, int k0, bool diag,
                              float* __restrict__ Gb, int L, int i0, int j0) {
    __shared__ __align__(16) __nv_bfloat16 smA_h[64][72];
    __shared__ __align__(16) __nv_bfloat16 smA_l[64][72];
    __shared__ __align__(16) __nv_bfloat16 smB_h[64][72];
    __shared__ __align__(16) __nv_bfloat16 smB_l[64][72];

    const int tid = threadIdx.x;
    const int lane = tid & 31;
    const int w = tid >> 5;
    const int wm = w >> 1, wn = w & 1;

    __nv_bfloat16 (*Bsh)[72] = diag ? smA_h : smB_h;
    __nv_bfloat16 (*Bsl)[72] = diag ? smA_l : smB_l;

    float acc[2][4][4];
#pragma unroll
    for (int mb = 0; mb < 2; mb++)
#pragma unroll
        for (int nb = 0; nb < 4; nb++)
#pragma unroll
            for (int i = 0; i < 4; i++) acc[mb][nb][i] = 0.f;

    const int arow = wm * 32 + (lane & 15);
    const int acol0 = (lane >> 4) << 3;
    const int brow = wn * 32 + (lane & 7) + ((lane & 16) >> 1);
    const int bcol0 = lane & 8;

    for (int kc = k0; kc < k0 + 4096; kc += 64) {
        __syncthreads();
#pragma unroll
        for (int u = 0; u < 4; u++) {
            int idx = u * 128 + tid;
            int r = idx >> 3, q = idx & 7;
            size_t off = (size_t)r * ldK + kc + q * 8;
            *(uint4*)&smA_h[r][q * 8] = *(const uint4*)(Ah + off);
            *(uint4*)&smA_l[r][q * 8] = *(const uint4*)(Al + off);
            if (!diag) {
                *(uint4*)&smB_h[r][q * 8] = *(const uint4*)(Bh + off);
                *(uint4*)&smB_l[r][q * 8] = *(const uint4*)(Bl + off);
            }
        }
        __syncthreads();

#pragma unroll
        for (int s = 0; s < 4; s++) {
            const int ks = s * 16;
            unsigned int ah[2][4], al[2][4], bh[2][4], bl[2][4];
            LDX4(ah[0], &smA_h[arow][ks + acol0]);
            LDX4(ah[1], &smA_h[arow + 16][ks + acol0]);
            LDX4(al[0], &smA_l[arow][ks + acol0]);
            LDX4(al[1], &smA_l[arow + 16][ks + acol0]);
            LDX4(bh[0], &Bsh[brow][ks + bcol0]);
            LDX4(bh[1], &Bsh[brow + 16][ks + bcol0]);
            LDX4(bl[0], &Bsl[brow][ks + bcol0]);
            LDX4(bl[1], &Bsl[brow + 16][ks + bcol0]);
#pragma unroll
            for (int mb = 0; mb < 2; mb++) {
#pragma unroll
                for (int nb = 0; nb < 4; nb++) {
                    unsigned int b0h = bh[nb >> 1][(nb & 1) * 2], b1h = bh[nb >> 1][(nb & 1) * 2 + 1];
                    unsigned int b0l = bl[nb >> 1][(nb & 1) * 2], b1l = bl[nb >> 1][(nb & 1) * 2 + 1];
                    MMA16816(acc[mb][nb], ah[mb], b0h, b1h);
                    MMA16816(acc[mb][nb], ah[mb], b0l, b1l);
                    MMA16816(acc[mb][nb], al[mb], b0h, b1h);
                }
            }
        }
    }

    // epilogue: write tile + mirror
#pragma unroll
    for (int mb = 0; mb < 2; mb++) {
#pragma unroll
        for (int nb = 0; nb < 4; nb++) {
            int gi = i0 + wm * 32 + mb * 16 + (lane >> 2);
            int gj = j0 + wn * 32 + nb * 8 + (lane & 3) * 2;
            float c0 = acc[mb][nb][0], c1 = acc[mb][nb][1];
            float c2 = acc[mb][nb][2], c3 = acc[mb][nb][3];
            Gb[(size_t)gi * L + gj]       = c0;
            Gb[(size_t)gi * L + gj + 1]   = c1;
            Gb[(size_t)(gi + 8) * L + gj]     = c2;
            Gb[(size_t)(gi + 8) * L + gj + 1] = c3;
            if (!diag) {
                Gb[(size_t)gj * L + gi]           = c0;
                Gb[(size_t)(gj + 1) * L + gi]     = c1;
                Gb[(size_t)gj * L + gi + 8]       = c2;
                Gb[(size_t)(gj + 1) * L + gi + 8] = c3;
            }
        }
    }
}

// combos: 0..23 time (2 mats x 6 pairs x 2 ksplit), 24..41 freq (2 mats x 3 pairs x 3 ksplit)
__global__ __launch_bounds__(128, 4) void gram_mma_kernel() {
    const int bx = blockIdx.x;
    const int b  = blockIdx.y;
    if (bx < 24) {
        int mat = bx / 12, r = bx % 12, pair = r % 6, kp = r / 6;
        const __nv_bfloat16* Mh = (mat ? g_AT_t_hi : g_AT_s_hi) + (size_t)b * LT * DT;
        const __nv_bfloat16* Ml = (mat ? g_AT_t_lo : g_AT_s_lo) + (size_t)b * LT * DT;
        float* out = (mat ? g_pTt : g_pTs) + (size_t)kp * (B_ * LT * LT) + (size_t)b * LT * LT;
        int i0 = c_tpi[pair] * 64, j0 = c_tpj[pair] * 64;
        gram_mma_body(Mh + (size_t)i0 * DT, Ml + (size_t)i0 * DT,
                      Mh + (size_t)j0 * DT, Ml + (size_t)j0 * DT,
                      DT, kp * 4096, i0 == j0, out, LT, i0, j0);
    } else {
        int e = bx - 24;
        int mat = e / 9, r = e % 9, pair = r % 3, kp = r / 3;
        const __nv_bfloat16* Mh = (mat ? g_AF_t_hi : g_AF_s_hi) + (size_t)b * LF * DF;
        const __nv_bfloat16* Ml = (mat ? g_AF_t_lo : g_AF_s_lo) + (size_t)b * LF * DF;
        float* out = (mat ? g_pFt : g_pFs) + (size_t)kp * (B_ * LF * LF) + (size_t)b * LF * LF;
        int i0 = c_fpi[pair] * 64, j0 = c_fpj[pair] * 64;
        gram_mma_body(Mh + (size_t)i0 * DF, Ml + (size_t)i0 * DF,
                      Mh + (size_t)j0 * DF, Ml + (size_t)j0 * DF,
                      DF, kp * 4096, i0 == j0, out, LF, i0, j0);
    }
}

// ---------------- finalize: normalize, (P+1)/2, rowmean, softmax, logP, ent ----------------
template <int L, int NP>
__global__ void finalize_kernel(const float* __restrict__ Gp,
                                float* __restrict__ logP, float* __restrict__ PtrT,
                                float* __restrict__ ent, float* __restrict__ rm) {
    const int s = blockIdx.x, b = blockIdx.y, j = threadIdx.x;
    __shared__ float invn[L];
    __shared__ float red[L / 32];
    const int MM = L * L;

    float gd = Gp[(size_t)b * MM + (size_t)j * L + j];
#pragma unroll
    for (int p = 1; p < NP; p++)
        gd += Gp[(size_t)p * B_ * MM + (size_t)b * MM + (size_t)j * L + j];
    invn[j] = 1.0f / fmaxf(sqrtf(gd), 1e-8f);
    __syncthreads();

    float g = Gp[(size_t)b * MM + (size_t)s * L + j];
#pragma unroll
    for (int p = 1; p < NP; p++)
        g += Gp[(size_t)p * B_ * MM + (size_t)b * MM + (size_t)s * L + j];
    float P = (g * invn[s] * invn[j] + 1.0f) * 0.5f;

    float rsum = blockReduceSum<L / 32>(P, red);
    float mx   = blockReduceMax<L / 32>(P, red);
    float e    = expf(P - mx);
    float Z    = blockReduceSum<L / 32>(e, red);
    float p    = e / Z;                       // softmax
    float lp   = logf(p + 2e-8f);             // log(softmax + EPS + EPS)
    logP[(size_t)b * MM + (size_t)s * L + j] = lp;
    PtrT[(size_t)b * MM + (size_t)j * L + s] = p + 1e-8f;   // transposed Prow (+EPS)
    float es = blockReduceSum<L / 32>((p + 1e-8f) * lp, red);
    if (j == 0) {
        ent[b * L + s] = es;
        rm[b * L + s]  = rsum * (1.0f / (float)L);
    }
}

// ---------------- tiny MLP: Linear(1,4) + ReLU + LayerNorm(4) ----------------
__global__ void mlp_kernel(const float* __restrict__ rm, const float* __restrict__ W,
                           const float* __restrict__ bv, const float* __restrict__ gv,
                           const float* __restrict__ betav, float* __restrict__ outq, int n) {
    int i = blockIdx.x * 256 + threadIdx.x;
    if (i >= n) return;
    float x = rm[i];
    float h[4];
#pragma unroll
    for (int t = 0; t < 4; t++) h[t] = fmaxf(fmaf(x, W[t], bv[t]), 0.f);
    float mu = 0.25f * (h[0] + h[1] + h[2] + h[3]);
    float v = 0.f;
#pragma unroll
    for (int t = 0; t < 4; t++) { float d = h[t] - mu; v = fmaf(d, d, v); }
    v *= 0.25f;
    float inv = 1.0f / sqrtf(v + 1e-5f);
#pragma unroll
    for (int t = 0; t < 4; t++) outq[i * 4 + t] = gv[t] * (h[t] - mu) * inv + betav[t];
}

// ---------------- loss: alpha softmax + weighted KL, one block per (b, s) ----------------
template <int L>
__global__ void loss_kernel(const float* __restrict__ q, const float* __restrict__ kk,
                            const float* __restrict__ logPs, const float* __restrict__ PtT,
                            const float* __restrict__ ent, float* __restrict__ partials,
                            float invden) {
    const int s = blockIdx.x, b = blockIdx.y, t = threadIdx.x;
    __shared__ float sh_lp[L];
    __shared__ float red[L / 32];
    const int MM = L * L;

    sh_lp[t] = logPs[(size_t)b * MM + (size_t)s * L + t];
    const float* qs = q + (b * L + s) * 4;
    const float* kt = kk + (b * L + t) * 4;
    float attn = (qs[0] * kt[0] + qs[1] * kt[1] + qs[2] * kt[2] + qs[3] * kt[3]) * 0.5f;
    __syncthreads();

    float mx = blockReduceMax<L / 32>(attn, red);
    float e  = expf(attn - mx);
    float Z  = blockReduceSum<L / 32>(e, red);

    float cross = 0.f;
    const float* Pt = PtT + (size_t)b * MM;     // [k][t] layout -> coalesced over t
#pragma unroll 4
    for (int k2 = 0; k2 < L; k2++) cross = fmaf(Pt[(size_t)k2 * L + t], sh_lp[k2], cross);

    float val = e * (ent[b * L + t] - cross);
    float S = blockReduceSum<L / 32>(val, red);
    if (t == 0) partials[b * L + s] = (S / Z) * invden;
}

// ---------------- final deterministic reduce ----------------
__global__ void reduce_kernel(const float* __restrict__ partials, int n, float* __restrict__ out) {
    __shared__ float red[8];
    float v = 0.f;
    for (int i = threadIdx.x; i < n; i += 256) v += partials[i];
    float S = blockReduceSum<8>(v, red);
    if (threadIdx.x == 0) out[0] = S;
}

// ---------------- launch ----------------
extern "C" void kernel_launch(void* const* d_in, const int* in_sizes, int n_in,
                              void* d_out, int out_size) {
    const float* fs  = (const float*)d_in[0];
    const float* ft  = (const float*)d_in[1];
    const float* WqT = (const float*)d_in[2];
    const float* bqT = (const float*)d_in[3];
    const float* gqT = (const float*)d_in[4];
    const float* BqT = (const float*)d_in[5];
    const float* WkT = (const float*)d_in[6];
    const float* bkT = (const float*)d_in[7];
    const float* gkT = (const float*)d_in[8];
    const float* BkT = (const float*)d_in[9];
    const float* WqF = (const float*)d_in[10];
    const float* bqF = (const float*)d_in[11];
    const float* gqF = (const float*)d_in[12];
    const float* BqF = (const float*)d_in[13];
    const float* WkF = (const float*)d_in[14];
    const float* bkF = (const float*)d_in[15];
    const float* gkF = (const float*)d_in[16];
    const float* BkF = (const float*)d_in[17];
    float* out = (float*)d_out;

    float *pTs, *pTt, *pFs, *pFt;
    float *lpTs, *ptTs, *lpTt, *ptTt, *lpFs, *ptFs, *lpFt, *ptFt;
    float *enTs, *enTt, *enFs, *enFt, *rmTs, *rmTt, *rmFs, *rmFt;
    float *qT, *kT, *qF, *kF, *parts;
    cudaGetSymbolAddress((void**)&pTs, g_pTs);
    cudaGetSymbolAddress((void**)&pTt, g_pTt);
    cudaGetSymbolAddress((void**)&pFs, g_pFs);
    cudaGetSymbolAddress((void**)&pFt, g_pFt);
    cudaGetSymbolAddress((void**)&lpTs, g_logP_Ts);
    cudaGetSymbolAddress((void**)&ptTs, g_PtrT_Ts);
    cudaGetSymbolAddress((void**)&lpTt, g_logP_Tt);
    cudaGetSymbolAddress((void**)&ptTt, g_PtrT_Tt);
    cudaGetSymbolAddress((void**)&lpFs, g_logP_Fs);
    cudaGetSymbolAddress((void**)&ptFs, g_PtrT_Fs);
    cudaGetSymbolAddress((void**)&lpFt, g_logP_Ft);
    cudaGetSymbolAddress((void**)&ptFt, g_PtrT_Ft);
    cudaGetSymbolAddress((void**)&enTs, g_ent_Ts);
    cudaGetSymbolAddress((void**)&enTt, g_ent_Tt);
    cudaGetSymbolAddress((void**)&enFs, g_ent_Fs);
    cudaGetSymbolAddress((void**)&enFt, g_ent_Ft);
    cudaGetSymbolAddress((void**)&rmTs, g_rm_Ts);
    cudaGetSymbolAddress((void**)&rmTt, g_rm_Tt);
    cudaGetSymbolAddress((void**)&rmFs, g_rm_Fs);
    cudaGetSymbolAddress((void**)&rmFt, g_rm_Ft);
    cudaGetSymbolAddress((void**)&qT, g_qT);
    cudaGetSymbolAddress((void**)&kT, g_kT);
    cudaGetSymbolAddress((void**)&qF, g_qF);
    cudaGetSymbolAddress((void**)&kF, g_kF);
    cudaGetSymbolAddress((void**)&parts, g_partials);

    // 1) prepass: fp32 -> bf16 hi/lo in both layouts
    prep_kernel<<<dim3(384, 8, 2), 256>>>(fs, ft);

    // 2) all four grams in one tensor-core launch: 42 combos x 8 batches
    gram_mma_kernel<<<dim3(42, B_), 128>>>();

    // 3) finalize each matrix (sum split-K partials deterministically)
    finalize_kernel<LT, 2><<<dim3(LT, B_), LT>>>(pTs, lpTs, ptTs, enTs, rmTs);
    finalize_kernel<LT, 2><<<dim3(LT, B_), LT>>>(pTt, lpTt, ptTt, enTt, rmTt);
    finalize_kernel<LF, 3><<<dim3(LF, B_), LF>>>(pFs, lpFs, ptFs, enFs, rmFs);
    finalize_kernel<LF, 3><<<dim3(LF, B_), LF>>>(pFt, lpFt, ptFt, enFt, rmFt);

    // 4) tiny MLPs
    const int nT = B_ * LT, nF = B_ * LF;
    mlp_kernel<<<(nT + 255) / 256, 256>>>(rmTs, WqT, bqT, gqT, BqT, qT, nT);
    mlp_kernel<<<(nT + 255) / 256, 256>>>(rmTt, WkT, bkT, gkT, BkT, kT, nT);
    mlp_kernel<<<(nF + 255) / 256, 256>>>(rmFs, WqF, bqF, gqF, BqF, qF, nF);
    mlp_kernel<<<(nF + 255) / 256, 256>>>(rmFt, WkF, bkF, gkF, BkF, kF, nF);

    // 5) attention-weighted KL
    const float invdenT = (float)(1.0 / ((double)B_ * LT * LT + 1e-8));
    const float invdenF = (float)(1.0 / ((double)B_ * LF * LF + 1e-8));
    loss_kernel<LT><<<dim3(LT, B_), LT>>>(qT, kT, lpTs, ptTt, enTt, parts, invdenT);
    loss_kernel<LF><<<dim3(LF, B_), LF>>>(qF, kF, lpFs, ptFt, enFt, parts + nT, invdenF);

    // 6) deterministic final reduce
    reduce_kernel<<<1, 256>>>(parts, nT + nF, out);
}